// round 13
// baseline (speedup 1.0000x reference)
#include <cuda_runtime.h>
#include <cuda_fp16.h>
#include <math.h>

// ---------------- problem constants ----------------
constexpr int NN = 100000;   // nodes
constexpr int EE = 1600000;  // edges
constexpr int CC = 25000;    // clusters
constexpr int GG = 64;       // graphs
constexpr int HH = 128;      // hidden / feature dim
constexpr int PPB = 16;      // prepool blocks per graph

// ---------------- zero-region layout (32-bit words) ----------------
constexpr int OFF_DEGN    = 0;
constexpr int OFF_CNTC    = OFF_DEGN + NN;
constexpr int OFF_DEGP    = OFF_CNTC + CC;
constexpr int OFF_CNTPG   = OFF_DEGP + CC;
constexpr int OFF_POSTSUM = OFF_CNTPG + GG;
constexpr int OFF_POSTMAX = OFF_POSTSUM + GG * HH;
constexpr int OFF_PRESUM  = OFF_POSTMAX + GG * HH;
constexpr int OFF_PREMAX  = OFF_PRESUM + GG * HH;
constexpr int ZTOT        = OFF_PREMAX + GG * HH;
static_assert(OFF_POSTSUM % 4 == 0, "postsum must be float4-aligned");

// ---------------- device scratch ----------------
__device__ __align__(16) unsigned int g_zbuf[ZTOT];
__device__ __align__(16) __half g_h0h[(size_t)NN * HH];  // conv1 gemm out (fp16)
__device__ __align__(16) __half g_hh [(size_t)NN * HH];  // conv1 out (fp16)
__device__ __align__(16) __half g_hw [CC * HH];          // pooled gemm out (fp16)
__device__ __align__(16) __half g_hph [CC * HH];         // cluster means (fp16)
__device__ __align__(16) __half g_hp2h[CC * HH];         // conv2 out (fp16)
__device__ int2  g_ssN[EE];          // {src, bits(disN[src])} sorted by dst
__device__ int2  g_ssP[EE];          // {src_p, bits(disP[src_p])} sorted by dst_p
__device__ int   g_memb[NN];         // node ids sorted by cluster
__device__ int   g_rowptrN[NN + 1], g_rowptrC[CC + 1], g_rowptrCL[CC + 1];
__device__ int   g_auxN[128], g_auxC[128], g_auxCL[128];
__device__ int   g_clus[NN], g_batch[NN], g_batchp[CC];
__device__ float g_disN[NN], g_disP[CC];
__device__ int   g_is64;

#define P_DEGN    ((int*)  (g_zbuf + OFF_DEGN))
#define P_CNTC    ((int*)  (g_zbuf + OFF_CNTC))
#define P_DEGP    ((int*)  (g_zbuf + OFF_DEGP))
#define P_CNTPG   ((int*)  (g_zbuf + OFF_CNTPG))
#define P_POSTSUM ((float*)(g_zbuf + OFF_POSTSUM))
#define P_POSTMAX ((float*)(g_zbuf + OFF_POSTMAX))
#define P_PRESUM  ((float*)(g_zbuf + OFF_PRESUM))
#define P_PREMAX  ((float*)(g_zbuf + OFF_PREMAX))

__device__ __forceinline__ void red_add_v4(float* addr, float4 v) {
    asm volatile("red.global.add.v4.f32 [%0], {%1,%2,%3,%4};"
                 :: "l"(addr), "f"(v.x), "f"(v.y), "f"(v.z), "f"(v.w)
                 : "memory");
}
__device__ __forceinline__ void red_add_f(float* addr, float v) {
    asm volatile("red.global.add.f32 [%0], %1;" :: "l"(addr), "f"(v) : "memory");
}
__device__ __forceinline__ unsigned int f2tf(float f) {
    unsigned int r;
    asm("cvt.rna.tf32.f32 %0, %1;" : "=r"(r) : "f"(f));
    return r;
}
__device__ __forceinline__ long long readi(const void* p, long long i, int is64) {
    return is64 ? ((const long long*)p)[i] : (long long)((const int*)p)[i];
}
__device__ __forceinline__ float4 h4f(uint2 r) {
    __half2 a = *(__half2*)&r.x;
    __half2 b = *(__half2*)&r.y;
    float2 fa = __half22float2(a), fb = __half22float2(b);
    return make_float4(fa.x, fa.y, fb.x, fb.y);
}
__device__ __forceinline__ uint2 f4h(float4 v) {
    __half2 a = __float22half2_rn(make_float2(v.x, v.y));
    __half2 b = __float22half2_rn(make_float2(v.z, v.w));
    uint2 r; r.x = *(unsigned int*)&a; r.y = *(unsigned int*)&b;
    return r;
}
__device__ __forceinline__ void fma4(float4& a, float4 v, float n) {
    a.x += v.x * n; a.y += v.y * n; a.z += v.z * n; a.w += v.w * n;
}

// 4-way unrolled latency-pipelined neighbor gather (int2 {src, dis_bits} records)
__device__ __forceinline__ float4 gather_nbrs(const __half* __restrict__ hin,
                                              const int2* __restrict__ ss,
                                              int e0, int e1, float dn, int lane,
                                              float4 a) {
    int e = e0;
    for (; e + 4 <= e1; e += 4) {
        int2 s0 = ss[e], s1 = ss[e + 1], s2 = ss[e + 2], s3 = ss[e + 3];
        uint2 r0 = ((const uint2*)(hin + (size_t)s0.x * HH))[lane];
        uint2 r1 = ((const uint2*)(hin + (size_t)s1.x * HH))[lane];
        uint2 r2 = ((const uint2*)(hin + (size_t)s2.x * HH))[lane];
        uint2 r3 = ((const uint2*)(hin + (size_t)s3.x * HH))[lane];
        fma4(a, h4f(r0), __int_as_float(s0.y) * dn);
        fma4(a, h4f(r1), __int_as_float(s1.y) * dn);
        fma4(a, h4f(r2), __int_as_float(s2.y) * dn);
        fma4(a, h4f(r3), __int_as_float(s3.y) * dn);
    }
    for (; e < e1; e++) {
        int2 sv = ss[e];
        uint2 r = ((const uint2*)(hin + (size_t)sv.x * HH))[lane];
        fma4(a, h4f(r), __int_as_float(sv.y) * dn);
    }
    return a;
}

// ---------------- kernels ----------------

__global__ void k_zero(const void* ei) {
    if (blockIdx.x == 0 && threadIdx.x == 0) {
        const long long* q = (const long long*)ei;
        int ok = 1;
        for (int i = 0; i < 64; i++) {
            long long v = q[i];
            if (v < 0 || v >= (long long)NN) { ok = 0; break; }
        }
        g_is64 = ok;  // int32 reinterpreted as int64 -> huge values a.s.
    }
    for (int i = blockIdx.x * blockDim.x + threadIdx.x; i < ZTOT;
         i += gridDim.x * blockDim.x)
        g_zbuf[i] = 0u;
}

// fused node prep + edge degree counting. Edge half reads cl[] directly
// (L2-resident) to avoid ordering on g_clus. Vector load only when both
// lanes are strictly in range; scalar fallback otherwise (OOB-safe).
__global__ void k_prep(const void* __restrict__ ei, const void* __restrict__ cl,
                       const void* __restrict__ ba, int N, int E) {
    int is64 = g_is64;
    int nbE = ((E >> 1) + 255) >> 8;   // 2 edges per thread
    int b = blockIdx.x;
    if (b < nbE) {
        int e = (b * 256 + threadIdx.x) * 2;
        if (e >= E) return;
        if (e + 1 < E) {
            int d0, d1;
            if (is64) {
                longlong2 v = ((const longlong2*)((const long long*)ei + E))[e >> 1];
                d0 = (int)v.x; d1 = (int)v.y;
            } else {
                int2 v = ((const int2*)((const int*)ei + E))[e >> 1];
                d0 = v.x; d1 = v.y;
            }
            atomicAdd(&P_DEGN[d0], 1);
            atomicAdd(&P_DEGP[(int)readi(cl, d0, is64)], 1);
            atomicAdd(&P_DEGN[d1], 1);
            atomicAdd(&P_DEGP[(int)readi(cl, d1, is64)], 1);
        } else {
            int d0 = (int)readi(ei, (long long)E + e, is64);
            atomicAdd(&P_DEGN[d0], 1);
            atomicAdd(&P_DEGP[(int)readi(cl, d0, is64)], 1);
        }
    } else {
        int n = (b - nbE) * 256 + threadIdx.x;
        if (n >= N) return;
        int c = (int)readi(cl, n, is64);
        g_clus[n]  = c;
        g_batch[n] = (int)readi(ba, n, is64);
        atomicAdd(&P_CNTC[c], 1);
    }
}

// ---- fused 3-array exclusive scan (1024 elems/block) + dis computation ----
__global__ void k_scanf_block(int N, int C) {
    __shared__ int sh[256];
    int bN = (N + 1023) >> 10, bC = (C + 1023) >> 10;
    int b = blockIdx.x, t = threadIdx.x;
    const int* in; int* out; float* dis; int* aux; int n; int lb;
    if (b < bN)           { in = P_DEGN; out = g_rowptrN;  dis = g_disN; aux = g_auxN;  n = N; lb = b; }
    else if (b < bN + bC) { in = P_DEGP; out = g_rowptrC;  dis = g_disP; aux = g_auxC;  n = C; lb = b - bN; }
    else                  { in = P_CNTC; out = g_rowptrCL; dis = 0;      aux = g_auxCL; n = C; lb = b - bN - bC; }
    int base = lb * 1024 + t * 4;
    int v[4]; int s = 0;
#pragma unroll
    for (int i = 0; i < 4; i++) {
        v[i] = (base + i < n) ? in[base + i] : 0;
        if (dis && base + i < n) dis[base + i] = rsqrtf((float)v[i] + 1.0f);
        s += v[i];
    }
    sh[t] = s;
    __syncthreads();
    for (int off = 1; off < 256; off <<= 1) {
        int x = (t >= off) ? sh[t - off] : 0;
        __syncthreads();
        sh[t] += x;
        __syncthreads();
    }
    int run = sh[t] - s;
#pragma unroll
    for (int i = 0; i < 4; i++) {
        if (base + i < n) out[base + i] = run;
        run += v[i];
    }
    if (t == 255) aux[lb] = sh[255];
}

__global__ void k_scanf_aux(int N, int C) {
    int bN = (N + 1023) >> 10, bC = (C + 1023) >> 10;
    int t = threadIdx.x;
    if (t == 0) {
        int run = 0;
        for (int i = 0; i < bN; i++) { int v = g_auxN[i]; g_auxN[i] = run; run += v; }
    } else if (t == 32) {
        int run = 0;
        for (int i = 0; i < bC; i++) { int v = g_auxC[i]; g_auxC[i] = run; run += v; }
    } else if (t == 64) {
        int run = 0;
        for (int i = 0; i < bC; i++) { int v = g_auxCL[i]; g_auxCL[i] = run; run += v; }
    }
}

__global__ void k_scanf_add(int N, int C, int E) {
    int bA = (N + 255) >> 8, bB = (C + 255) >> 8;
    int b = blockIdx.x, t = threadIdx.x;
    if (b < bA) {
        int i = b * 256 + t;
        if (i < N) g_rowptrN[i] += g_auxN[i >> 10];
        if (i == 0) g_rowptrN[N] = E;
    } else if (b < bA + bB) {
        int i = (b - bA) * 256 + t;
        if (i < C) g_rowptrC[i] += g_auxC[i >> 10];
        if (i == 0) g_rowptrC[C] = E;
    } else {
        int i = (b - bA - bB) * 256 + t;
        if (i < C) g_rowptrCL[i] += g_auxCL[i >> 10];
        if (i == 0) g_rowptrCL[C] = N;
    }
}

// fused bucket placement (edges -> ssN/ssP, nodes -> memb) with destructive
// rowptr cursors: afterwards rowptr[d] == end(d); row d = [rowptr[d-1], rowptr[d]).
__global__ void k_placeall(const void* __restrict__ ei, int N, int E) {
    int ebl = (E + 255) >> 8;
    int b = blockIdx.x;
    if (b < ebl) {
        int e = b * 256 + threadIdx.x;
        if (e >= E) return;
        int is64 = g_is64;
        int s = (int)readi(ei, e, is64);
        int d = (int)readi(ei, (long long)E + e, is64);
        int2 rec; rec.x = s; rec.y = __float_as_int(g_disN[s]);
        g_ssN[atomicAdd(&g_rowptrN[d], 1)] = rec;
        int sp = g_clus[s], dp = g_clus[d];
        int2 recp; recp.x = sp; recp.y = __float_as_int(g_disP[sp]);
        g_ssP[atomicAdd(&g_rowptrC[dp], 1)] = recp;
    } else {
        int n = (b - ebl) * 256 + threadIdx.x;
        if (n >= N) return;
        g_memb[atomicAdd(&g_rowptrCL[g_clus[n]], 1)] = n;
    }
}

// ---- TF32 tensor-core GEMM: Out[M,128] = A[M,128] @ W[128,128] ----
template <typename InT, typename OutT>
__global__ void k_gemm_tc(const InT* __restrict__ A, const float* __restrict__ W,
                          OutT* __restrict__ Out, int M) {
    __shared__ unsigned int As[128][36];
    __shared__ unsigned int Ws[32][136];
    int t = threadIdx.x;
    int wid = t >> 5, lane = t & 31;
    int grp = lane >> 2, thr = lane & 3;
    int wm = (wid & 3) * 32;
    int wn = (wid >> 2) * 64;
    int row0 = blockIdx.x * 128;

    float c[2][8][4];
#pragma unroll
    for (int m = 0; m < 2; m++)
#pragma unroll
        for (int n = 0; n < 8; n++)
#pragma unroll
            for (int i = 0; i < 4; i++) c[m][n][i] = 0.f;

    for (int kc = 0; kc < 4; kc++) {
        {
            int idx = t;
#pragma unroll
            for (int r4 = 0; r4 < 4; r4++, idx += 256) {
                int row = idx >> 3, c4 = idx & 7;
                int gr = row0 + row;
                float4 v;
                if (gr < M) {
                    if constexpr (sizeof(InT) == 2) {
                        uint2 rv = ((const uint2*)((const __half*)A + (size_t)gr * 128 + kc * 32))[c4];
                        v = h4f(rv);
                    } else {
                        v = ((const float4*)((const float*)A + (size_t)gr * 128 + kc * 32))[c4];
                    }
                } else {
                    v = make_float4(0.f, 0.f, 0.f, 0.f);
                }
                As[row][c4 * 4 + 0] = f2tf(v.x);
                As[row][c4 * 4 + 1] = f2tf(v.y);
                As[row][c4 * 4 + 2] = f2tf(v.z);
                As[row][c4 * 4 + 3] = f2tf(v.w);
            }
        }
        {
            int idx = t;
#pragma unroll
            for (int r4 = 0; r4 < 4; r4++, idx += 256) {
                int kr = idx >> 5, c4 = idx & 31;
                float4 v = ((const float4*)(W + (size_t)(kc * 32 + kr) * 128))[c4];
                Ws[kr][c4 * 4 + 0] = f2tf(v.x);
                Ws[kr][c4 * 4 + 1] = f2tf(v.y);
                Ws[kr][c4 * 4 + 2] = f2tf(v.z);
                Ws[kr][c4 * 4 + 3] = f2tf(v.w);
            }
        }
        __syncthreads();
#pragma unroll
        for (int ks = 0; ks < 4; ks++) {
            int k0 = ks * 8;
            unsigned int a[2][4];
#pragma unroll
            for (int m = 0; m < 2; m++) {
                int rb = wm + m * 16;
                a[m][0] = As[rb + grp    ][k0 + thr    ];
                a[m][1] = As[rb + grp + 8][k0 + thr    ];
                a[m][2] = As[rb + grp    ][k0 + thr + 4];
                a[m][3] = As[rb + grp + 8][k0 + thr + 4];
            }
#pragma unroll
            for (int nt = 0; nt < 8; nt++) {
                int n0 = wn + nt * 8;
                unsigned int b0 = Ws[k0 + thr    ][n0 + grp];
                unsigned int b1 = Ws[k0 + thr + 4][n0 + grp];
#pragma unroll
                for (int m = 0; m < 2; m++) {
                    asm volatile(
                        "mma.sync.aligned.m16n8k8.row.col.f32.tf32.tf32.f32 "
                        "{%0,%1,%2,%3}, {%4,%5,%6,%7}, {%8,%9}, {%0,%1,%2,%3};"
                        : "+f"(c[m][nt][0]), "+f"(c[m][nt][1]),
                          "+f"(c[m][nt][2]), "+f"(c[m][nt][3])
                        : "r"(a[m][0]), "r"(a[m][1]), "r"(a[m][2]), "r"(a[m][3]),
                          "r"(b0), "r"(b1));
                }
            }
        }
        __syncthreads();
    }
#pragma unroll
    for (int m = 0; m < 2; m++) {
#pragma unroll
        for (int nt = 0; nt < 8; nt++) {
            int col = wn + nt * 8 + thr * 2;
            int gr0 = row0 + wm + m * 16 + grp;
            int gr1 = gr0 + 8;
            if constexpr (sizeof(OutT) == 2) {
                if (gr0 < M) {
                    __half2 v = __float22half2_rn(make_float2(c[m][nt][0], c[m][nt][1]));
                    *(__half2*)((__half*)Out + (size_t)gr0 * 128 + col) = v;
                }
                if (gr1 < M) {
                    __half2 v = __float22half2_rn(make_float2(c[m][nt][2], c[m][nt][3]));
                    *(__half2*)((__half*)Out + (size_t)gr1 * 128 + col) = v;
                }
            } else {
                if (gr0 < M)
                    *(float2*)((float*)Out + (size_t)gr0 * 128 + col) =
                        make_float2(c[m][nt][0], c[m][nt][1]);
                if (gr1 < M)
                    *(float2*)((float*)Out + (size_t)gr1 * 128 + col) =
                        make_float2(c[m][nt][2], c[m][nt][3]);
            }
        }
    }
}

// ---- persistent CSR gather conv (fp16 -> fp16): one warp per dst row ----
__global__ void __launch_bounds__(256)
k_conv_gather(const __half* __restrict__ hin, const float* __restrict__ b,
              __half* __restrict__ hout,
              const int* __restrict__ rowptr, const int2* __restrict__ ss,
              const float* __restrict__ dis, int M) {
    int wtot = (gridDim.x * blockDim.x) >> 5;
    int lane = threadIdx.x & 31;
    float4 bv = ((const float4*)b)[lane];
    for (int n = (blockIdx.x * blockDim.x + threadIdx.x) >> 5; n < M; n += wtot) {
        float dn = dis[n];
        float4 a = h4f(((const uint2*)(hin + (size_t)n * HH))[lane]);
        float d2 = dn * dn;
        a.x *= d2; a.y *= d2; a.z *= d2; a.w *= d2;
        int e1 = rowptr[n];
        int e0 = n ? rowptr[n - 1] : 0;
        a = gather_nbrs(hin, ss, e0, e1, dn, lane, a);
        a.x = fmaxf(a.x + bv.x, 0.f);
        a.y = fmaxf(a.y + bv.y, 0.f);
        a.z = fmaxf(a.z + bv.z, 0.f);
        a.w = fmaxf(a.w + bv.w, 0.f);
        ((uint2*)(hout + (size_t)n * HH))[lane] = f4h(a);
    }
}

// cluster mean pooling via membership CSR (persistent, fp16 out)
__global__ void __launch_bounds__(256)
k_hp(const __half* __restrict__ h, __half* __restrict__ hp, int C) {
    int wtot = (gridDim.x * blockDim.x) >> 5;
    int lane = threadIdx.x & 31;
    for (int c = (blockIdx.x * blockDim.x + threadIdx.x) >> 5; c < C; c += wtot) {
        int m1 = g_rowptrCL[c];
        int m0 = c ? g_rowptrCL[c - 1] : 0;
        float4 a = make_float4(0.f, 0.f, 0.f, 0.f);
        int bmax = 0;
        int i = m0;
        for (; i + 4 <= m1; i += 4) {
            int n0 = g_memb[i], n1 = g_memb[i + 1], n2 = g_memb[i + 2], n3 = g_memb[i + 3];
            uint2 r0 = ((const uint2*)(h + (size_t)n0 * HH))[lane];
            uint2 r1 = ((const uint2*)(h + (size_t)n1 * HH))[lane];
            uint2 r2 = ((const uint2*)(h + (size_t)n2 * HH))[lane];
            uint2 r3 = ((const uint2*)(h + (size_t)n3 * HH))[lane];
            bmax = max(bmax, max(max(g_batch[n0], g_batch[n1]), max(g_batch[n2], g_batch[n3])));
            fma4(a, h4f(r0), 1.f); fma4(a, h4f(r1), 1.f);
            fma4(a, h4f(r2), 1.f); fma4(a, h4f(r3), 1.f);
        }
        for (; i < m1; i++) {
            int node = g_memb[i];
            bmax = max(bmax, g_batch[node]);
            fma4(a, h4f(((const uint2*)(h + (size_t)node * HH))[lane]), 1.f);
        }
        int cnt = m1 - m0;
        float sc = 1.0f / (float)(cnt > 0 ? cnt : 1);
        a.x *= sc; a.y *= sc; a.z *= sc; a.w *= sc;
        ((uint2*)(hp + (size_t)c * HH))[lane] = f4h(a);
        if (lane == 0) {
            g_batchp[c] = bmax;
            atomicAdd(&P_CNTPG[bmax], 1);
        }
    }
}

// conv3: gather + relu fused with post pooling (sum + max over batch_p)
__global__ void __launch_bounds__(256)
k_convp_post(const __half* __restrict__ hin, const float* __restrict__ b, int C) {
    int wtot = (gridDim.x * blockDim.x) >> 5;
    int lane = threadIdx.x & 31;
    float4 bv = ((const float4*)b)[lane];
    for (int n = (blockIdx.x * blockDim.x + threadIdx.x) >> 5; n < C; n += wtot) {
        float dn = g_disP[n];
        float4 a = h4f(((const uint2*)(hin + (size_t)n * HH))[lane]);
        float d2 = dn * dn;
        a.x *= d2; a.y *= d2; a.z *= d2; a.w *= d2;
        int e1 = g_rowptrC[n];
        int e0 = n ? g_rowptrC[n - 1] : 0;
        a = gather_nbrs(hin, g_ssP, e0, e1, dn, lane, a);
        a.x = fmaxf(a.x + bv.x, 0.f);
        a.y = fmaxf(a.y + bv.y, 0.f);
        a.z = fmaxf(a.z + bv.z, 0.f);
        a.w = fmaxf(a.w + bv.w, 0.f);
        int g = g_batchp[n];
        red_add_v4(P_POSTSUM + (size_t)g * HH + lane * 4, a);
        int* pm = (int*)(P_POSTMAX + (size_t)g * HH + lane * 4);
        atomicMax(pm + 0, __float_as_int(a.x));
        atomicMax(pm + 1, __float_as_int(a.y));
        atomicMax(pm + 2, __float_as_int(a.z));
        atomicMax(pm + 3, __float_as_int(a.w));
    }
}

// pre-pool partial mean/max over fp16 h (PPB blocks per graph)
__global__ void k_prepool(const __half* __restrict__ h, int N) {
    int g = blockIdx.x / PPB;
    int chunk = blockIdx.x % PPB;
    int j = threadIdx.x;  // 128
    int lo = 0, hi = N;
    while (lo < hi) { int m = (lo + hi) >> 1; if (g_batch[m] < g) lo = m + 1; else hi = m; }
    int s = lo;
    lo = s; hi = N;
    while (lo < hi) { int m = (lo + hi) >> 1; if (g_batch[m] < g + 1) lo = m + 1; else hi = m; }
    int e = lo;
    int len = e - s;
    int c0 = s + (int)((long long)len * chunk / PPB);
    int c1 = s + (int)((long long)len * (chunk + 1) / PPB);
    float sum = 0.f, mx = 0.f;
#pragma unroll 8
    for (int n = c0; n < c1; n++) {
        float v = __half2float(h[(size_t)n * HH + j]);
        sum += v;
        mx = fmaxf(mx, v);
    }
    if (c1 > c0) {
        red_add_f(P_PRESUM + g * HH + j, sum);
        atomicMax((int*)(P_PREMAX + g * HH + j), __float_as_int(mx));
    }
}

// final MLP + log_softmax (one block per graph)
__global__ void k_final(const float* __restrict__ l1w, const float* __restrict__ l1b,
                        const float* __restrict__ l2w, const float* __restrict__ l2b,
                        float* __restrict__ out, int N) {
    __shared__ float zs[512];
    __shared__ float ys[128];
    __shared__ float os[10];
    int g = blockIdx.x, j = threadIdx.x;
    int lo = 0, hi = N;
    while (lo < hi) { int m = (lo + hi) >> 1; if (g_batch[m] < g) lo = m + 1; else hi = m; }
    int s = lo;
    lo = s; hi = N;
    while (lo < hi) { int m = (lo + hi) >> 1; if (g_batch[m] < g + 1) lo = m + 1; else hi = m; }
    int cntN = lo - s;
    int cpg = P_CNTPG[g];
    zs[j]       = P_PRESUM[g * HH + j] / (float)(cntN > 0 ? cntN : 1);
    zs[128 + j] = P_PREMAX[g * HH + j];
    zs[256 + j] = P_POSTSUM[g * HH + j] / (float)(cpg > 0 ? cpg : 1);
    zs[384 + j] = P_POSTMAX[g * HH + j];
    __syncthreads();
    float acc = l1b[j];
#pragma unroll 8
    for (int k = 0; k < 512; k++) acc += zs[k] * l1w[k * 128 + j];
    ys[j] = fmaxf(acc, 0.f);
    __syncthreads();
    if (j < 10) {
        float a = l2b[j];
#pragma unroll 8
        for (int k = 0; k < 128; k++) a += ys[k] * l2w[k * 10 + j];
        os[j] = a;
    }
    __syncthreads();
    if (j < 10) {
        float m = os[0];
#pragma unroll
        for (int i = 1; i < 10; i++) m = fmaxf(m, os[i]);
        float ssum = 0.f;
#pragma unroll
        for (int i = 0; i < 10; i++) ssum += expf(os[i] - m);
        out[g * 10 + j] = os[j] - m - logf(ssum);
    }
}

// ---------------- host launcher ----------------
extern "C" void kernel_launch(void* const* d_in, const int* in_sizes, int n_in,
                              void* d_out, int out_size) {
    const float* x   = (const float*)d_in[0];
    const void*  ei  = d_in[1];
    const void*  ba  = d_in[2];
    const void*  cl  = d_in[3];
    const float* W1  = (const float*)d_in[6];
    const float* b1  = (const float*)d_in[7];
    const float* W2  = (const float*)d_in[8];
    const float* b2  = (const float*)d_in[9];
    const float* W3  = (const float*)d_in[10];
    const float* b3  = (const float*)d_in[11];
    const float* l1w = (const float*)d_in[12];
    const float* l1b = (const float*)d_in[13];
    const float* l2w = (const float*)d_in[14];
    const float* l2b = (const float*)d_in[15];
    float* out = (float*)d_out;

    int N = in_sizes[0] / HH;
    int E = in_sizes[1] / 2;
    int C = CC;
    (void)n_in; (void)out_size;

    // side stream + events (created on the first, uncaptured, call)
    static cudaStream_t sB = 0;
    static cudaEvent_t evRoot = 0, evB = 0, evG = 0, evPre = 0;
    if (!sB) {
        cudaStreamCreateWithFlags(&sB, cudaStreamNonBlocking);
        cudaEventCreateWithFlags(&evRoot, cudaEventDisableTiming);
        cudaEventCreateWithFlags(&evB,    cudaEventDisableTiming);
        cudaEventCreateWithFlags(&evG,    cudaEventDisableTiming);
        cudaEventCreateWithFlags(&evPre,  cudaEventDisableTiming);
    }

    void* p;
    cudaGetSymbolAddress(&p, g_h0h);     __half* h0h = (__half*)p;
    cudaGetSymbolAddress(&p, g_hh);      __half* hh  = (__half*)p;
    cudaGetSymbolAddress(&p, g_hw);      __half* hw  = (__half*)p;
    cudaGetSymbolAddress(&p, g_hph);     __half* hp  = (__half*)p;
    cudaGetSymbolAddress(&p, g_hp2h);    __half* hp2 = (__half*)p;
    cudaGetSymbolAddress(&p, g_rowptrN); int* rpN    = (int*)p;
    cudaGetSymbolAddress(&p, g_rowptrC); int* rpC    = (int*)p;
    cudaGetSymbolAddress(&p, g_ssN);     int2* ssN   = (int2*)p;
    cudaGetSymbolAddress(&p, g_ssP);     int2* ssP   = (int2*)p;
    cudaGetSymbolAddress(&p, g_disN);    float* dN   = (float*)p;
    cudaGetSymbolAddress(&p, g_disP);    float* dP   = (float*)p;

    const int T = 256;
    const int PG = 1184;                 // persistent gather grid (148 SMs x 8)
    int ebl = (E + T - 1) / T;
    int nbl = (N + T - 1) / T;
    int e2bl = ((E / 2) + T - 1) / T;    // 2 edges per thread
    int bN1024 = (N + 1023) / 1024, bC1024 = (C + 1023) / 1024;
    int bN256 = (N + 255) / 256, bC256 = (C + 255) / 256;

    // fork: conv1 GEMM (depends only on inputs) overlaps the prep chain
    cudaEventRecord(evRoot, 0);
    cudaStreamWaitEvent(sB, evRoot, 0);
    k_gemm_tc<float, __half><<<(N + 127) / 128, 256, 0, sB>>>(x, W1, h0h, N);
    cudaEventRecord(evB, sB);

    // main chain: zero + fused prep + fused CSR build
    k_zero<<<256, T>>>(ei);
    k_prep<<<e2bl + nbl, T>>>(ei, cl, ba, N, E);
    k_scanf_block<<<bN1024 + 2 * bC1024, 256>>>(N, C);
    k_scanf_aux<<<1, 96>>>(N, C);
    k_scanf_add<<<bN256 + 2 * bC256, 256>>>(N, C, E);
    k_placeall<<<ebl + nbl, T>>>(ei, N, E);

    // conv1 gather (needs edge CSR + gemm1)
    cudaStreamWaitEvent(0, evB, 0);
    k_conv_gather<<<PG, T>>>(h0h, b1, hh, rpN, ssN, dN, N);

    // fork: prepool overlaps cluster mean + conv2
    cudaEventRecord(evG, 0);
    cudaStreamWaitEvent(sB, evG, 0);
    k_prepool<<<GG * PPB, 128, 0, sB>>>(hh, N);
    cudaEventRecord(evPre, sB);

    // cluster mean (batch_p, CNTPG)
    k_hp<<<PG, T>>>(hh, hp, C);

    // conv2
    k_gemm_tc<__half, __half><<<(C + 127) / 128, 256>>>(hp, W2, hw, C);
    k_conv_gather<<<PG, T>>>(hw, b2, hp2, rpC, ssP, dP, C);

    // conv3 (fused post pooling)
    k_gemm_tc<__half, __half><<<(C + 127) / 128, 256>>>(hp2, W3, hw, C);
    k_convp_post<<<PG, T>>>(hw, b3, C);

    // MLP head + log_softmax (needs prepool partials)
    cudaStreamWaitEvent(0, evPre, 0);
    k_final<<<GG, 128>>>(l1w, l1b, l2w, l2b, out, N);
}

// round 14
// speedup vs baseline: 1.1251x; 1.1251x over previous
#include <cuda_runtime.h>
#include <cuda_fp16.h>
#include <math.h>

// ---------------- problem constants ----------------
constexpr int NN = 100000;   // nodes
constexpr int EE = 1600000;  // edges
constexpr int CC = 25000;    // clusters
constexpr int GG = 64;       // graphs
constexpr int HH = 128;      // hidden / feature dim
constexpr int PPB = 16;      // prepool blocks per graph
constexpr unsigned SRC_MASK = 0x1FFFFu;  // 17 bits for node/cluster index
static_assert(NN < (1 << 17), "src index must fit 17 bits");

// ---------------- zero-region layout (32-bit words) ----------------
constexpr int OFF_DEGN    = 0;
constexpr int OFF_CNTC    = OFF_DEGN + NN;
constexpr int OFF_DEGP    = OFF_CNTC + CC;
constexpr int OFF_CNTPG   = OFF_DEGP + CC;
constexpr int OFF_POSTSUM = OFF_CNTPG + GG;
constexpr int OFF_POSTMAX = OFF_POSTSUM + GG * HH;
constexpr int OFF_PRESUM  = OFF_POSTMAX + GG * HH;
constexpr int OFF_PREMAX  = OFF_PRESUM + GG * HH;
constexpr int ZTOT        = OFF_PREMAX + GG * HH;
static_assert(OFF_POSTSUM % 4 == 0, "postsum must be float4-aligned");

// ---------------- device scratch ----------------
__device__ __align__(16) unsigned int g_zbuf[ZTOT];
__device__ __align__(16) __half g_h0h[(size_t)NN * HH];  // conv1 gemm out (fp16)
__device__ __align__(16) __half g_hh [(size_t)NN * HH];  // conv1 out (fp16)
__device__ __align__(16) __half g_hw [CC * HH];          // pooled gemm out (fp16)
__device__ __align__(16) __half g_hph [CC * HH];         // cluster means (fp16)
__device__ __align__(16) __half g_hp2h[CC * HH];         // conv2 out (fp16)
__device__ unsigned g_ssN[EE];       // src | (deg<<17), sorted by dst
__device__ unsigned g_ssP[EE];       // src_p | (deg_p<<17), sorted by dst_p
__device__ int   g_memb[NN];         // node ids sorted by cluster
__device__ int   g_rowptrN[NN + 1], g_rowptrC[CC + 1], g_rowptrCL[CC + 1];
__device__ int   g_auxN[128], g_auxC[128], g_auxCL[128];
__device__ int   g_clus[NN], g_batch[NN], g_batchp[CC];
__device__ float g_disN[NN], g_disP[CC];
__device__ int   g_is64;

#define P_DEGN    ((int*)  (g_zbuf + OFF_DEGN))
#define P_CNTC    ((int*)  (g_zbuf + OFF_CNTC))
#define P_DEGP    ((int*)  (g_zbuf + OFF_DEGP))
#define P_CNTPG   ((int*)  (g_zbuf + OFF_CNTPG))
#define P_POSTSUM ((float*)(g_zbuf + OFF_POSTSUM))
#define P_POSTMAX ((float*)(g_zbuf + OFF_POSTMAX))
#define P_PRESUM  ((float*)(g_zbuf + OFF_PRESUM))
#define P_PREMAX  ((float*)(g_zbuf + OFF_PREMAX))

__device__ __forceinline__ void red_add_v4(float* addr, float4 v) {
    asm volatile("red.global.add.v4.f32 [%0], {%1,%2,%3,%4};"
                 :: "l"(addr), "f"(v.x), "f"(v.y), "f"(v.z), "f"(v.w)
                 : "memory");
}
__device__ __forceinline__ void red_add_f(float* addr, float v) {
    asm volatile("red.global.add.f32 [%0], %1;" :: "l"(addr), "f"(v) : "memory");
}
__device__ __forceinline__ unsigned int f2tf(float f) {
    unsigned int r;
    asm("cvt.rna.tf32.f32 %0, %1;" : "=r"(r) : "f"(f));
    return r;
}
__device__ __forceinline__ long long readi(const void* p, long long i, int is64) {
    return is64 ? ((const long long*)p)[i] : (long long)((const int*)p)[i];
}
__device__ __forceinline__ float4 h4f(uint2 r) {
    __half2 a = *(__half2*)&r.x;
    __half2 b = *(__half2*)&r.y;
    float2 fa = __half22float2(a), fb = __half22float2(b);
    return make_float4(fa.x, fa.y, fb.x, fb.y);
}
__device__ __forceinline__ uint2 f4h(float4 v) {
    __half2 a = __float22half2_rn(make_float2(v.x, v.y));
    __half2 b = __float22half2_rn(make_float2(v.z, v.w));
    uint2 r; r.x = *(unsigned int*)&a; r.y = *(unsigned int*)&b;
    return r;
}
__device__ __forceinline__ void fma4(float4& a, float4 v, float n) {
    a.x += v.x * n; a.y += v.y * n; a.z += v.z * n; a.w += v.w * n;
}
__device__ __forceinline__ float unpack_nrm(unsigned v, float dn) {
    return rsqrtf((float)(v >> 17) + 1.0f) * dn;
}

// 4-way unrolled latency-pipelined neighbor gather (packed uint records)
__device__ __forceinline__ float4 gather_nbrs(const __half* __restrict__ hin,
                                              const unsigned* __restrict__ ss,
                                              int e0, int e1, float dn, int lane,
                                              float4 a) {
    int e = e0;
    for (; e + 4 <= e1; e += 4) {
        unsigned v0 = ss[e], v1 = ss[e + 1], v2 = ss[e + 2], v3 = ss[e + 3];
        uint2 r0 = ((const uint2*)(hin + (size_t)(v0 & SRC_MASK) * HH))[lane];
        uint2 r1 = ((const uint2*)(hin + (size_t)(v1 & SRC_MASK) * HH))[lane];
        uint2 r2 = ((const uint2*)(hin + (size_t)(v2 & SRC_MASK) * HH))[lane];
        uint2 r3 = ((const uint2*)(hin + (size_t)(v3 & SRC_MASK) * HH))[lane];
        fma4(a, h4f(r0), unpack_nrm(v0, dn));
        fma4(a, h4f(r1), unpack_nrm(v1, dn));
        fma4(a, h4f(r2), unpack_nrm(v2, dn));
        fma4(a, h4f(r3), unpack_nrm(v3, dn));
    }
    for (; e < e1; e++) {
        unsigned v = ss[e];
        uint2 r = ((const uint2*)(hin + (size_t)(v & SRC_MASK) * HH))[lane];
        fma4(a, h4f(r), unpack_nrm(v, dn));
    }
    return a;
}

// ---------------- kernels ----------------

__global__ void k_zero(const void* ei) {
    if (blockIdx.x == 0 && threadIdx.x == 0) {
        const long long* q = (const long long*)ei;
        int ok = 1;
        for (int i = 0; i < 64; i++) {
            long long v = q[i];
            if (v < 0 || v >= (long long)NN) { ok = 0; break; }
        }
        g_is64 = ok;  // int32 reinterpreted as int64 -> huge values a.s.
    }
    for (int i = blockIdx.x * blockDim.x + threadIdx.x; i < ZTOT;
         i += gridDim.x * blockDim.x)
        g_zbuf[i] = 0u;
}

__global__ void k_prep_nodes(const void* __restrict__ cl, const void* __restrict__ ba, int N) {
    int n = blockIdx.x * blockDim.x + threadIdx.x;
    if (n >= N) return;
    int is64 = g_is64;
    int c = (int)readi(cl, n, is64);
    g_clus[n]  = c;
    g_batch[n] = (int)readi(ba, n, is64);
    atomicAdd(&P_CNTC[c], 1);
}

// degree counting only: reads just the dst half of edge_index
__global__ void k_prep_edges(const void* __restrict__ ei, int E) {
    int e = blockIdx.x * blockDim.x + threadIdx.x;
    if (e >= E) return;
    int d = (int)readi(ei, (long long)E + e, g_is64);
    atomicAdd(&P_DEGN[d], 1);
    atomicAdd(&P_DEGP[g_clus[d]], 1);
}

// ---- fused 3-array exclusive scan (1024 elems/block) + dis computation ----
__global__ void k_scanf_block(int N, int C) {
    __shared__ int sh[256];
    int bN = (N + 1023) >> 10, bC = (C + 1023) >> 10;
    int b = blockIdx.x, t = threadIdx.x;
    const int* in; int* out; float* dis; int* aux; int n; int lb;
    if (b < bN)           { in = P_DEGN; out = g_rowptrN;  dis = g_disN; aux = g_auxN;  n = N; lb = b; }
    else if (b < bN + bC) { in = P_DEGP; out = g_rowptrC;  dis = g_disP; aux = g_auxC;  n = C; lb = b - bN; }
    else                  { in = P_CNTC; out = g_rowptrCL; dis = 0;      aux = g_auxCL; n = C; lb = b - bN - bC; }
    int base = lb * 1024 + t * 4;
    int v[4]; int s = 0;
#pragma unroll
    for (int i = 0; i < 4; i++) {
        v[i] = (base + i < n) ? in[base + i] : 0;
        if (dis && base + i < n) dis[base + i] = rsqrtf((float)v[i] + 1.0f);
        s += v[i];
    }
    sh[t] = s;
    __syncthreads();
    for (int off = 1; off < 256; off <<= 1) {
        int x = (t >= off) ? sh[t - off] : 0;
        __syncthreads();
        sh[t] += x;
        __syncthreads();
    }
    int run = sh[t] - s;
#pragma unroll
    for (int i = 0; i < 4; i++) {
        if (base + i < n) out[base + i] = run;
        run += v[i];
    }
    if (t == 255) aux[lb] = sh[255];
}

__global__ void k_scanf_aux(int N, int C) {
    int bN = (N + 1023) >> 10, bC = (C + 1023) >> 10;
    int t = threadIdx.x;
    if (t == 0) {
        int run = 0;
        for (int i = 0; i < bN; i++) { int v = g_auxN[i]; g_auxN[i] = run; run += v; }
    } else if (t == 32) {
        int run = 0;
        for (int i = 0; i < bC; i++) { int v = g_auxC[i]; g_auxC[i] = run; run += v; }
    } else if (t == 64) {
        int run = 0;
        for (int i = 0; i < bC; i++) { int v = g_auxCL[i]; g_auxCL[i] = run; run += v; }
    }
}

__global__ void k_scanf_add(int N, int C, int E) {
    int bA = (N + 255) >> 8, bB = (C + 255) >> 8;
    int b = blockIdx.x, t = threadIdx.x;
    if (b < bA) {
        int i = b * 256 + t;
        if (i < N) g_rowptrN[i] += g_auxN[i >> 10];
        if (i == 0) g_rowptrN[N] = E;
    } else if (b < bA + bB) {
        int i = (b - bA) * 256 + t;
        if (i < C) g_rowptrC[i] += g_auxC[i >> 10];
        if (i == 0) g_rowptrC[C] = E;
    } else {
        int i = (b - bA - bB) * 256 + t;
        if (i < C) g_rowptrCL[i] += g_auxCL[i >> 10];
        if (i == 0) g_rowptrCL[C] = N;
    }
}

// bucket placement with destructive rowptr cursors: after this kernel
// rowptr[d] == end(d); row d spans [rowptr[d-1], rowptr[d]) with row0 start 0.
__global__ void k_place(const void* __restrict__ ei, int E) {
    int e = blockIdx.x * blockDim.x + threadIdx.x;
    if (e >= E) return;
    int is64 = g_is64;
    int s = (int)readi(ei, e, is64);
    int d = (int)readi(ei, (long long)E + e, is64);
    unsigned recN = (unsigned)s | ((unsigned)P_DEGN[s] << 17);
    g_ssN[atomicAdd(&g_rowptrN[d], 1)] = recN;
    int sp = g_clus[s], dp = g_clus[d];
    unsigned recP = (unsigned)sp | ((unsigned)P_DEGP[sp] << 17);
    g_ssP[atomicAdd(&g_rowptrC[dp], 1)] = recP;
}

__global__ void k_place_nodes(int N) {
    int n = blockIdx.x * blockDim.x + threadIdx.x;
    if (n >= N) return;
    g_memb[atomicAdd(&g_rowptrCL[g_clus[n]], 1)] = n;
}

// ---- TF32 tensor-core GEMM: Out[M,128] = A[M,128] @ W[128,128] ----
template <typename InT, typename OutT>
__global__ void k_gemm_tc(const InT* __restrict__ A, const float* __restrict__ W,
                          OutT* __restrict__ Out, int M) {
    __shared__ unsigned int As[128][36];
    __shared__ unsigned int Ws[32][136];
    int t = threadIdx.x;
    int wid = t >> 5, lane = t & 31;
    int grp = lane >> 2, thr = lane & 3;
    int wm = (wid & 3) * 32;
    int wn = (wid >> 2) * 64;
    int row0 = blockIdx.x * 128;

    float c[2][8][4];
#pragma unroll
    for (int m = 0; m < 2; m++)
#pragma unroll
        for (int n = 0; n < 8; n++)
#pragma unroll
            for (int i = 0; i < 4; i++) c[m][n][i] = 0.f;

    for (int kc = 0; kc < 4; kc++) {
        {
            int idx = t;
#pragma unroll
            for (int r4 = 0; r4 < 4; r4++, idx += 256) {
                int row = idx >> 3, c4 = idx & 7;
                int gr = row0 + row;
                float4 v;
                if (gr < M) {
                    if constexpr (sizeof(InT) == 2) {
                        uint2 rv = ((const uint2*)((const __half*)A + (size_t)gr * 128 + kc * 32))[c4];
                        v = h4f(rv);
                    } else {
                        v = ((const float4*)((const float*)A + (size_t)gr * 128 + kc * 32))[c4];
                    }
                } else {
                    v = make_float4(0.f, 0.f, 0.f, 0.f);
                }
                As[row][c4 * 4 + 0] = f2tf(v.x);
                As[row][c4 * 4 + 1] = f2tf(v.y);
                As[row][c4 * 4 + 2] = f2tf(v.z);
                As[row][c4 * 4 + 3] = f2tf(v.w);
            }
        }
        {
            int idx = t;
#pragma unroll
            for (int r4 = 0; r4 < 4; r4++, idx += 256) {
                int kr = idx >> 5, c4 = idx & 31;
                float4 v = ((const float4*)(W + (size_t)(kc * 32 + kr) * 128))[c4];
                Ws[kr][c4 * 4 + 0] = f2tf(v.x);
                Ws[kr][c4 * 4 + 1] = f2tf(v.y);
                Ws[kr][c4 * 4 + 2] = f2tf(v.z);
                Ws[kr][c4 * 4 + 3] = f2tf(v.w);
            }
        }
        __syncthreads();
#pragma unroll
        for (int ks = 0; ks < 4; ks++) {
            int k0 = ks * 8;
            unsigned int a[2][4];
#pragma unroll
            for (int m = 0; m < 2; m++) {
                int rb = wm + m * 16;
                a[m][0] = As[rb + grp    ][k0 + thr    ];
                a[m][1] = As[rb + grp + 8][k0 + thr    ];
                a[m][2] = As[rb + grp    ][k0 + thr + 4];
                a[m][3] = As[rb + grp + 8][k0 + thr + 4];
            }
#pragma unroll
            for (int nt = 0; nt < 8; nt++) {
                int n0 = wn + nt * 8;
                unsigned int b0 = Ws[k0 + thr    ][n0 + grp];
                unsigned int b1 = Ws[k0 + thr + 4][n0 + grp];
#pragma unroll
                for (int m = 0; m < 2; m++) {
                    asm volatile(
                        "mma.sync.aligned.m16n8k8.row.col.f32.tf32.tf32.f32 "
                        "{%0,%1,%2,%3}, {%4,%5,%6,%7}, {%8,%9}, {%0,%1,%2,%3};"
                        : "+f"(c[m][nt][0]), "+f"(c[m][nt][1]),
                          "+f"(c[m][nt][2]), "+f"(c[m][nt][3])
                        : "r"(a[m][0]), "r"(a[m][1]), "r"(a[m][2]), "r"(a[m][3]),
                          "r"(b0), "r"(b1));
                }
            }
        }
        __syncthreads();
    }
#pragma unroll
    for (int m = 0; m < 2; m++) {
#pragma unroll
        for (int nt = 0; nt < 8; nt++) {
            int col = wn + nt * 8 + thr * 2;
            int gr0 = row0 + wm + m * 16 + grp;
            int gr1 = gr0 + 8;
            if constexpr (sizeof(OutT) == 2) {
                if (gr0 < M) {
                    __half2 v = __float22half2_rn(make_float2(c[m][nt][0], c[m][nt][1]));
                    *(__half2*)((__half*)Out + (size_t)gr0 * 128 + col) = v;
                }
                if (gr1 < M) {
                    __half2 v = __float22half2_rn(make_float2(c[m][nt][2], c[m][nt][3]));
                    *(__half2*)((__half*)Out + (size_t)gr1 * 128 + col) = v;
                }
            } else {
                if (gr0 < M)
                    *(float2*)((float*)Out + (size_t)gr0 * 128 + col) =
                        make_float2(c[m][nt][0], c[m][nt][1]);
                if (gr1 < M)
                    *(float2*)((float*)Out + (size_t)gr1 * 128 + col) =
                        make_float2(c[m][nt][2], c[m][nt][3]);
            }
        }
    }
}

// ---- CSR gather conv (fp16 in -> fp16 out): one warp per dst row ----
__global__ void k_conv_gather(const __half* __restrict__ hin, const float* __restrict__ b,
                              __half* __restrict__ hout,
                              const int* __restrict__ rowptr, const unsigned* __restrict__ ss,
                              const float* __restrict__ dis, int M) {
    int n = (blockIdx.x * blockDim.x + threadIdx.x) >> 5;
    int lane = threadIdx.x & 31;
    if (n >= M) return;
    float dn = dis[n];
    float4 a = h4f(((const uint2*)(hin + (size_t)n * HH))[lane]);
    float d2 = dn * dn;
    a.x *= d2; a.y *= d2; a.z *= d2; a.w *= d2;
    int e1 = rowptr[n];
    int e0 = n ? rowptr[n - 1] : 0;
    a = gather_nbrs(hin, ss, e0, e1, dn, lane, a);
    float4 bv = ((const float4*)b)[lane];
    a.x = fmaxf(a.x + bv.x, 0.f);
    a.y = fmaxf(a.y + bv.y, 0.f);
    a.z = fmaxf(a.z + bv.z, 0.f);
    a.w = fmaxf(a.w + bv.w, 0.f);
    ((uint2*)(hout + (size_t)n * HH))[lane] = f4h(a);
}

// cluster mean pooling via membership CSR (fp16 out)
__global__ void k_hp(const __half* __restrict__ h, __half* __restrict__ hp, int C) {
    int c = (blockIdx.x * blockDim.x + threadIdx.x) >> 5;
    int lane = threadIdx.x & 31;
    if (c >= C) return;
    int m1 = g_rowptrCL[c];
    int m0 = c ? g_rowptrCL[c - 1] : 0;
    float4 a = make_float4(0.f, 0.f, 0.f, 0.f);
    int bmax = 0;
    int i = m0;
    for (; i + 4 <= m1; i += 4) {
        int n0 = g_memb[i], n1 = g_memb[i + 1], n2 = g_memb[i + 2], n3 = g_memb[i + 3];
        uint2 r0 = ((const uint2*)(h + (size_t)n0 * HH))[lane];
        uint2 r1 = ((const uint2*)(h + (size_t)n1 * HH))[lane];
        uint2 r2 = ((const uint2*)(h + (size_t)n2 * HH))[lane];
        uint2 r3 = ((const uint2*)(h + (size_t)n3 * HH))[lane];
        bmax = max(bmax, max(max(g_batch[n0], g_batch[n1]), max(g_batch[n2], g_batch[n3])));
        fma4(a, h4f(r0), 1.f); fma4(a, h4f(r1), 1.f);
        fma4(a, h4f(r2), 1.f); fma4(a, h4f(r3), 1.f);
    }
    for (; i < m1; i++) {
        int node = g_memb[i];
        bmax = max(bmax, g_batch[node]);
        fma4(a, h4f(((const uint2*)(h + (size_t)node * HH))[lane]), 1.f);
    }
    int cnt = m1 - m0;
    float sc = 1.0f / (float)(cnt > 0 ? cnt : 1);
    a.x *= sc; a.y *= sc; a.z *= sc; a.w *= sc;
    ((uint2*)(hp + (size_t)c * HH))[lane] = f4h(a);
    if (lane == 0) {
        g_batchp[c] = bmax;
        atomicAdd(&P_CNTPG[bmax], 1);
    }
}

// conv3: gather + relu fused with post pooling (sum + max over batch_p)
__global__ void k_convp_post(const __half* __restrict__ hin, const float* __restrict__ b,
                             int C) {
    int n = (blockIdx.x * blockDim.x + threadIdx.x) >> 5;
    int lane = threadIdx.x & 31;
    if (n >= C) return;
    float dn = g_disP[n];
    float4 a = h4f(((const uint2*)(hin + (size_t)n * HH))[lane]);
    float d2 = dn * dn;
    a.x *= d2; a.y *= d2; a.z *= d2; a.w *= d2;
    int e1 = g_rowptrC[n];
    int e0 = n ? g_rowptrC[n - 1] : 0;
    a = gather_nbrs(hin, g_ssP, e0, e1, dn, lane, a);
    float4 bv = ((const float4*)b)[lane];
    a.x = fmaxf(a.x + bv.x, 0.f);
    a.y = fmaxf(a.y + bv.y, 0.f);
    a.z = fmaxf(a.z + bv.z, 0.f);
    a.w = fmaxf(a.w + bv.w, 0.f);
    int g = g_batchp[n];
    red_add_v4(P_POSTSUM + (size_t)g * HH + lane * 4, a);
    int* pm = (int*)(P_POSTMAX + (size_t)g * HH + lane * 4);
    atomicMax(pm + 0, __float_as_int(a.x));
    atomicMax(pm + 1, __float_as_int(a.y));
    atomicMax(pm + 2, __float_as_int(a.z));
    atomicMax(pm + 3, __float_as_int(a.w));
}

// pre-pool partial mean/max over fp16 h (PPB blocks per graph)
__global__ void k_prepool(const __half* __restrict__ h, int N) {
    int g = blockIdx.x / PPB;
    int chunk = blockIdx.x % PPB;
    int j = threadIdx.x;  // 128
    int lo = 0, hi = N;
    while (lo < hi) { int m = (lo + hi) >> 1; if (g_batch[m] < g) lo = m + 1; else hi = m; }
    int s = lo;
    lo = s; hi = N;
    while (lo < hi) { int m = (lo + hi) >> 1; if (g_batch[m] < g + 1) lo = m + 1; else hi = m; }
    int e = lo;
    int len = e - s;
    int c0 = s + (int)((long long)len * chunk / PPB);
    int c1 = s + (int)((long long)len * (chunk + 1) / PPB);
    float sum = 0.f, mx = 0.f;
#pragma unroll 8
    for (int n = c0; n < c1; n++) {
        float v = __half2float(h[(size_t)n * HH + j]);
        sum += v;
        mx = fmaxf(mx, v);
    }
    if (c1 > c0) {
        red_add_f(P_PRESUM + g * HH + j, sum);
        atomicMax((int*)(P_PREMAX + g * HH + j), __float_as_int(mx));
    }
}

// final MLP + log_softmax (one block per graph)
__global__ void k_final(const float* __restrict__ l1w, const float* __restrict__ l1b,
                        const float* __restrict__ l2w, const float* __restrict__ l2b,
                        float* __restrict__ out, int N) {
    __shared__ float zs[512];
    __shared__ float ys[128];
    __shared__ float os[10];
    int g = blockIdx.x, j = threadIdx.x;
    int lo = 0, hi = N;
    while (lo < hi) { int m = (lo + hi) >> 1; if (g_batch[m] < g) lo = m + 1; else hi = m; }
    int s = lo;
    lo = s; hi = N;
    while (lo < hi) { int m = (lo + hi) >> 1; if (g_batch[m] < g + 1) lo = m + 1; else hi = m; }
    int cntN = lo - s;
    int cpg = P_CNTPG[g];
    zs[j]       = P_PRESUM[g * HH + j] / (float)(cntN > 0 ? cntN : 1);
    zs[128 + j] = P_PREMAX[g * HH + j];
    zs[256 + j] = P_POSTSUM[g * HH + j] / (float)(cpg > 0 ? cpg : 1);
    zs[384 + j] = P_POSTMAX[g * HH + j];
    __syncthreads();
    float acc = l1b[j];
#pragma unroll 8
    for (int k = 0; k < 512; k++) acc += zs[k] * l1w[k * 128 + j];
    ys[j] = fmaxf(acc, 0.f);
    __syncthreads();
    if (j < 10) {
        float a = l2b[j];
#pragma unroll 8
        for (int k = 0; k < 128; k++) a += ys[k] * l2w[k * 10 + j];
        os[j] = a;
    }
    __syncthreads();
    if (j < 10) {
        float m = os[0];
#pragma unroll
        for (int i = 1; i < 10; i++) m = fmaxf(m, os[i]);
        float ssum = 0.f;
#pragma unroll
        for (int i = 0; i < 10; i++) ssum += expf(os[i] - m);
        out[g * 10 + j] = os[j] - m - logf(ssum);
    }
}

// ---------------- host launcher ----------------
extern "C" void kernel_launch(void* const* d_in, const int* in_sizes, int n_in,
                              void* d_out, int out_size) {
    const float* x   = (const float*)d_in[0];
    const void*  ei  = d_in[1];
    const void*  ba  = d_in[2];
    const void*  cl  = d_in[3];
    const float* W1  = (const float*)d_in[6];
    const float* b1  = (const float*)d_in[7];
    const float* W2  = (const float*)d_in[8];
    const float* b2  = (const float*)d_in[9];
    const float* W3  = (const float*)d_in[10];
    const float* b3  = (const float*)d_in[11];
    const float* l1w = (const float*)d_in[12];
    const float* l1b = (const float*)d_in[13];
    const float* l2w = (const float*)d_in[14];
    const float* l2b = (const float*)d_in[15];
    float* out = (float*)d_out;

    int N = in_sizes[0] / HH;
    int E = in_sizes[1] / 2;
    int C = CC;
    (void)n_in; (void)out_size;

    // side stream + events (created on the first, uncaptured, call)
    static cudaStream_t sB = 0;
    static cudaEvent_t evRoot = 0, evB = 0, evG = 0, evPre = 0;
    if (!sB) {
        cudaStreamCreateWithFlags(&sB, cudaStreamNonBlocking);
        cudaEventCreateWithFlags(&evRoot, cudaEventDisableTiming);
        cudaEventCreateWithFlags(&evB,    cudaEventDisableTiming);
        cudaEventCreateWithFlags(&evG,    cudaEventDisableTiming);
        cudaEventCreateWithFlags(&evPre,  cudaEventDisableTiming);
    }

    void* p;
    cudaGetSymbolAddress(&p, g_h0h);     __half* h0h = (__half*)p;
    cudaGetSymbolAddress(&p, g_hh);      __half* hh  = (__half*)p;
    cudaGetSymbolAddress(&p, g_hw);      __half* hw  = (__half*)p;
    cudaGetSymbolAddress(&p, g_hph);     __half* hp  = (__half*)p;
    cudaGetSymbolAddress(&p, g_hp2h);    __half* hp2 = (__half*)p;
    cudaGetSymbolAddress(&p, g_rowptrN); int* rpN    = (int*)p;
    cudaGetSymbolAddress(&p, g_rowptrC); int* rpC    = (int*)p;
    cudaGetSymbolAddress(&p, g_ssN);     unsigned* ssN = (unsigned*)p;
    cudaGetSymbolAddress(&p, g_ssP);     unsigned* ssP = (unsigned*)p;
    cudaGetSymbolAddress(&p, g_disN);    float* dN   = (float*)p;
    cudaGetSymbolAddress(&p, g_disP);    float* dP   = (float*)p;

    const int T = 256;
    int ebl = (E + T - 1) / T;
    int nbl = (N + T - 1) / T;
    int nwb = (N + 7) / 8;
    int cwb = (C + 7) / 8;
    int bN1024 = (N + 1023) / 1024, bC1024 = (C + 1023) / 1024;
    int bN256 = (N + 255) / 256, bC256 = (C + 255) / 256;

    // fork: conv1 GEMM (depends only on inputs) overlaps the prep chain
    cudaEventRecord(evRoot, 0);
    cudaStreamWaitEvent(sB, evRoot, 0);
    k_gemm_tc<float, __half><<<(N + 127) / 128, 256, 0, sB>>>(x, W1, h0h, N);
    cudaEventRecord(evB, sB);

    // main chain: prep + fused CSR build
    k_zero<<<512, T>>>(ei);
    k_prep_nodes<<<nbl, T>>>(cl, ba, N);
    k_prep_edges<<<ebl, T>>>(ei, E);
    k_scanf_block<<<bN1024 + 2 * bC1024, 256>>>(N, C);
    k_scanf_aux<<<1, 96>>>(N, C);
    k_scanf_add<<<bN256 + 2 * bC256, 256>>>(N, C, E);
    k_place<<<ebl, T>>>(ei, E);
    k_place_nodes<<<nbl, T>>>(N);

    // conv1 gather (needs edge CSR + gemm1)
    cudaStreamWaitEvent(0, evB, 0);
    k_conv_gather<<<nwb, T>>>(h0h, b1, hh, rpN, ssN, dN, N);

    // fork: prepool overlaps cluster mean + conv2
    cudaEventRecord(evG, 0);
    cudaStreamWaitEvent(sB, evG, 0);
    k_prepool<<<GG * PPB, 128, 0, sB>>>(hh, N);
    cudaEventRecord(evPre, sB);

    // cluster mean (batch_p, CNTPG)
    k_hp<<<cwb, T>>>(hh, hp, C);

    // conv2
    k_gemm_tc<__half, __half><<<(C + 127) / 128, 256>>>(hp, W2, hw, C);
    k_conv_gather<<<cwb, T>>>(hw, b2, hp2, rpC, ssP, dP, C);

    // conv3 (fused post pooling)
    k_gemm_tc<__half, __half><<<(C + 127) / 128, 256>>>(hp2, W3, hw, C);
    k_convp_post<<<cwb, T>>>(hw, b3, C);

    // MLP head + log_softmax (needs prepool partials)
    cudaStreamWaitEvent(0, evPre, 0);
    k_final<<<GG, 128>>>(l1w, l1b, l2w, l2b, out, N);
}